// round 17
// baseline (speedup 1.0000x reference)
#include <cuda_runtime.h>
#include <math.h>

#define kB   64
#define kE   300
#define kH   512
#define kH4  2048
#define kPL  128
#define kHL  64
#define kC   3
#define kV   50000
#define NBLKP 296   // 2 blocks per SM; all resident

// ---------------- scratch ----------------
__device__ __align__(16) float g_GXTp[(size_t)kPL*kH4*kB];  // [t][n][b]
__device__ __align__(16) float g_GXTh[(size_t)kHL*kH4*kB];  // [t][n][b]
__device__ __align__(16) float g_outp[(size_t)kB*kPL*kH];   // [b][p][h]
__device__ __align__(16) float g_outh[(size_t)kB*kHL*kH];   // [b][t][h]
__device__ __align__(16) float g_a1  [(size_t)kB*kPL*kH];   // [b][p][h]
__device__ __align__(16) float g_qWhT[(size_t)kHL*kH*kB];   // [t][n][b]
__device__ __align__(16) float g_hT[2][kH*kB];              // [k][b]
__device__ __align__(16) float g_cT[2][kH*kB];              // [k][b]
__device__ __align__(16) float g_hn [kB*kH];
__device__ __align__(16) float g_r  [kB*kH];
__device__ __align__(16) float g_rT [kH*kB];                // [k][b]
__device__ __align__(16) float g_a2T[kH*kB];                // [n][b]
__device__ __align__(16) float g_rtT[kH*kB];                // [n][b]
__device__ __align__(16) float g_ss [kB*kPL];               // [b][p]
__device__ __align__(16) float g_rep[kB*kH];

// ---------------- bucketed grid barrier (8 counters, 296 = 8*37) -----------
__device__ unsigned g_cnt8[8];
__device__ unsigned g_master = 0;
__device__ volatile unsigned g_gen = 0;

__device__ __forceinline__ void grid_barrier() {
    __threadfence();
    __syncthreads();
    if (threadIdx.x == 0) {
        unsigned gen = g_gen;
        int bkt = blockIdx.x & 7;
        if (atomicAdd(&g_cnt8[bkt], 1u) == 37u - 1u) {
            g_cnt8[bkt] = 0;
            if (atomicAdd(&g_master, 1u) == 7u) {
                g_master = 0;
                __threadfence();
                g_gen = gen + 1;
            }
        }
        while (g_gen == gen) __nanosleep(32);
        __threadfence();
    }
    __syncthreads();
}

__device__ __forceinline__ float fsigmoid(float x) {
    return __fdividef(1.0f, 1.0f + __expf(-x));
}
__device__ __forceinline__ float ftanh(float x) {
    return 1.0f - __fdividef(2.0f, __expf(2.0f * x) + 1.0f);
}
__device__ __forceinline__ float htanh(float x) {
    float y;
    asm("tanh.approx.f32 %0, %1;" : "=f"(y) : "f"(x));
    return y;
}

__global__ void zero_init() {
    int i = blockIdx.x * blockDim.x + threadIdx.x;
    if (i < kB * kH) { g_hT[0][i] = 0.f; g_cT[0][i] = 0.f; g_rT[i] = 0.f; }
}
__global__ void zero_out_k(float* out, int n) {
    int i = blockIdx.x * blockDim.x + threadIdx.x;
    if (i < n) out[i] = 0.f;
}

// ---------------- GEMM 64x64 tile, 4x4 microtile (proven core) ------------
__global__ void __launch_bounds__(256) gemm64(
    int mode, const float* __restrict__ emb, const int* __restrict__ tok,
    const float* __restrict__ W, const float* __restrict__ bias1,
    const float* __restrict__ bias2, int N, int K, int T)
{
    __shared__ __align__(16) float As[32][68];
    __shared__ __align__(16) float Ws[32][68];

    int tid = threadIdx.x;
    int m0 = blockIdx.y * 64, n0 = blockIdx.x * 64;
    int lr  = tid & 63;
    int lks = (tid >> 6) << 3;

    const float* arow;
    if (mode <= 1) {
        int m = m0 + lr;
        int tt = m >> 6, bb = m & 63;
        int tk = tok[bb * T + tt];
        tk = (tk < 0) ? 0 : ((tk >= kV) ? (kV - 1) : tk);
        arow = emb + (size_t)tk * K;
    } else if (mode == 2) {
        arow = g_outp + (size_t)(m0 + lr) * K;
    } else {
        arow = g_outh + (size_t)(m0 + lr) * K;
    }
    const float* wrow = W + (size_t)(n0 + lr) * K;

    int tx = tid & 15, ty = tid >> 4;
    float acc[4][4] = {};

    for (int k0 = 0; k0 < K; k0 += 32) {
        __syncthreads();
#pragma unroll
        for (int kk2 = 0; kk2 < 8; kk2++) {
            int k = k0 + lks + kk2;
            As[lks + kk2][lr] = (k < K) ? arow[k] : 0.f;
            Ws[lks + kk2][lr] = (k < K) ? wrow[k] : 0.f;
        }
        __syncthreads();
#pragma unroll
        for (int kk = 0; kk < 32; kk++) {
            float4 a = *(const float4*)&As[kk][ty << 2];
            float4 w = *(const float4*)&Ws[kk][tx << 2];
            acc[0][0] += a.x*w.x; acc[0][1] += a.x*w.y; acc[0][2] += a.x*w.z; acc[0][3] += a.x*w.w;
            acc[1][0] += a.y*w.x; acc[1][1] += a.y*w.y; acc[1][2] += a.y*w.z; acc[1][3] += a.y*w.w;
            acc[2][0] += a.z*w.x; acc[2][1] += a.z*w.y; acc[2][2] += a.z*w.z; acc[2][3] += a.z*w.w;
            acc[3][0] += a.w*w.x; acc[3][1] += a.w*w.y; acc[3][2] += a.w*w.z; acc[3][3] += a.w*w.w;
        }
    }
#pragma unroll
    for (int i = 0; i < 4; i++) {
        int m = m0 + (ty << 2) + i;
#pragma unroll
        for (int j2 = 0; j2 < 4; j2++) {
            int n = n0 + (tx << 2) + j2;
            float v = acc[i][j2];
            if (bias1) v += bias1[n];
            if (bias2) v += bias2[n];
            if (mode == 0) {
                g_GXTp[((size_t)(m >> 6) * kH4 + n) * 64 + (m & 63)] = v;
            } else if (mode == 1) {
                g_GXTh[((size_t)(m >> 6) * kH4 + n) * 64 + (m & 63)] = v;
            } else if (mode == 2) {
                g_a1[(size_t)m * N + n] = v;
            } else {
                g_qWhT[((size_t)(m & 63) * kH + n) * 64 + (m >> 6)] = v;
            }
        }
    }
}

// ---------------- persistent LSTM, 2 blocks/SM -----------------------------
// 296 blocks x 256 thr; blocks 0..255 active, each owns 2 j's.
// thread: b = tid&63, q = tid>>6: jq = q>>1 (j select), gp = q&1 (gate pair).
// Computes gate rows {gp*2, gp*2+1} of j = blk*2 + jq. Gates exchanged in smem.
__global__ void __launch_bounds__(256, 2) lstm_persist(
    const float* __restrict__ Whh1, const float* __restrict__ Whh2)
{
    __shared__ __align__(16) float ws[8][512];    // 16KB: [jq*4+g][k]
    __shared__ __align__(16) float hsT[64][64];   // 16KB
    __shared__ float sg[2][4][64];                // 2KB gate exchange

    int tid = threadIdx.x;
    int b  = tid & 63;
    int q  = tid >> 6;
    int jq = q >> 1;
    int gp = q & 1;
    int blk = blockIdx.x;
    bool active = (blk < 256);
    int j  = (blk << 1) + jq;

    for (int phase = 0; phase < 2; phase++) {
        const float* __restrict__ Whh = phase ? Whh2 : Whh1;
        __syncthreads();
        if (active) {
            for (int idx = tid; idx < 8 * 128; idx += 256) {
                int row = idx >> 7;               // jql*4 + gl
                int jql = row >> 2, gl = row & 3;
                int c4  = (idx & 127) << 2;
                *(float4*)&ws[row][c4] = *(const float4*)(
                    Whh + (size_t)(gl * 512 + (blk << 1) + jql) * kH + c4);
            }
        }
        grid_barrier();

        const int T = phase ? kHL : kPL;
        const float* __restrict__ GXT = phase ? g_GXTh : g_GXTp;
        const float* wrA = ws[jq * 4 + gp * 2 + 0];
        const float* wrB = ws[jq * 4 + gp * 2 + 1];

        for (int t = 0; t < T; t++) {
            if (active) {
                const float* __restrict__ hT_in = g_hT[t & 1];

                float a0 = GXT[((size_t)t * kH4 + (gp * 2 + 0) * 512 + j) * 64 + b];
                float a1 = GXT[((size_t)t * kH4 + (gp * 2 + 1) * 512 + j) * 64 + b];

                float4 pre[4];
#pragma unroll
                for (int i2 = 0; i2 < 4; i2++) {
                    int lin = tid + (i2 << 8);
                    pre[i2] = __ldcg((const float4*)(hT_in +
                        (size_t)(lin >> 4) * 64 + ((lin & 15) << 2)));
                }

                for (int cch = 0; cch < 8; cch++) {
                    __syncthreads();
#pragma unroll
                    for (int i2 = 0; i2 < 4; i2++) {
                        int lin = tid + (i2 << 8);
                        *(float4*)&hsT[lin >> 4][(lin & 15) << 2] = pre[i2];
                    }
                    __syncthreads();
                    if (cch < 7) {
#pragma unroll
                        for (int i2 = 0; i2 < 4; i2++) {
                            int lin = tid + (i2 << 8);
                            pre[i2] = __ldcg((const float4*)(hT_in +
                                (size_t)((cch + 1) * 64 + (lin >> 4)) * 64 +
                                ((lin & 15) << 2)));
                        }
                    }
                    int kw = cch << 6;
#pragma unroll 8
                    for (int kk = 0; kk < 64; kk += 4) {
                        float h0 = hsT[kk+0][b], h1 = hsT[kk+1][b];
                        float h2 = hsT[kk+2][b], h3 = hsT[kk+3][b];
                        float4 u = *(const float4*)(wrA + kw + kk);
                        float4 v = *(const float4*)(wrB + kw + kk);
                        a0 += h0*u.x + h1*u.y + h2*u.z + h3*u.w;
                        a1 += h0*v.x + h1*v.y + h2*v.z + h3*v.w;
                    }
                }
                sg[jq][gp * 2 + 0][b] = a0;
                sg[jq][gp * 2 + 1][b] = a1;
            }
            __syncthreads();
            if (active && q < 2) {
                int jj = (blk << 1) + q;
                float gi = sg[q][0][b];
                float gf = sg[q][1][b];
                float gg = sg[q][2][b];
                float go = sg[q][3][b];
                float c = fsigmoid(gf) * g_cT[t & 1][jj * 64 + b] + fsigmoid(gi) * ftanh(gg);
                float h = fsigmoid(go) * ftanh(c);
                g_cT[(t + 1) & 1][jj * 64 + b] = c;
                g_hT[(t + 1) & 1][jj * 64 + b] = h;
                if (phase == 0) {
                    g_outp[((size_t)b * kPL + t) * kH + jj] = h;
                } else {
                    g_outh[((size_t)b * kHL + t) * kH + jj] = h;
                    if (t == kHL - 1) g_hn[b * kH + jj] = h;
                }
            }
            grid_barrier();
        }
        if (phase == 0) {
            if (active && q < 2) g_hT[0][((blk << 1) + q) * 64 + b] = 0.f;
            grid_barrier();
        }
    }
}

// ---------------- persistent attention, 2 blocks/SM ------------------------
// A: blocks 0..255, 4 rows each (0..127 -> Wr/a2; 128..255 -> Wt/rt).
// B1: blocks 0..255, (bb = blk>>2, quarter-p) each, tanh.approx scores.
// B2: blocks 0..63, softmax + r update.
__global__ void __launch_bounds__(256, 2) att_persist(
    const float* __restrict__ Wr, const float* __restrict__ Wt,
    const float* __restrict__ w_att)
{
    __shared__ __align__(16) float ws2[4][512];   // 8KB
    __shared__ __align__(16) float rsT[64][64];   // 16KB
    __shared__ float a2s[512];
    __shared__ float wvs[512];
    __shared__ float ss[128];
    __shared__ float red[8];

    int tid = threadIdx.x;
    int b  = tid & 63;
    int lr = tid >> 6;                 // 0..3 -> 1 row each
    int blk = blockIdx.x;
    bool activeA = (blk < 256);
    bool isA = (blk < 128);
    int rbase = blk << 2;

    if (activeA) {
        const float* Wsrc = isA ? Wr : Wt;
        int roff = isA ? rbase : (rbase - 512);
        for (int idx = tid; idx < 4 * 128; idx += 256) {
            int row = idx >> 7;
            int c4  = (idx & 127) << 2;
            *(float4*)&ws2[row][c4] = *(const float4*)(Wsrc + (size_t)(roff + row) * kH + c4);
        }
        for (int i = tid; i < 512; i += 256) wvs[i] = w_att[i];
    }
    grid_barrier();

    const float* w0 = ws2[lr];
    int r0g = rbase + lr;

    for (int t = 0; t < kHL; t++) {
        // ---- phase A: 1 weight row per thread over rT ----
        if (activeA) {
            float a0 = 0.f;
            float4 pre[4];
#pragma unroll
            for (int i2 = 0; i2 < 4; i2++) {
                int lin = tid + (i2 << 8);
                pre[i2] = __ldcg((const float4*)(g_rT +
                    (size_t)(lin >> 4) * 64 + ((lin & 15) << 2)));
            }
            for (int cch = 0; cch < 8; cch++) {
                __syncthreads();
#pragma unroll
                for (int i2 = 0; i2 < 4; i2++) {
                    int lin = tid + (i2 << 8);
                    *(float4*)&rsT[lin >> 4][(lin & 15) << 2] = pre[i2];
                }
                __syncthreads();
                if (cch < 7) {
#pragma unroll
                    for (int i2 = 0; i2 < 4; i2++) {
                        int lin = tid + (i2 << 8);
                        pre[i2] = __ldcg((const float4*)(g_rT +
                            (size_t)((cch + 1) * 64 + (lin >> 4)) * 64 +
                            ((lin & 15) << 2)));
                    }
                }
                int kw = cch << 6;
#pragma unroll 8
                for (int kk = 0; kk < 64; kk += 4) {
                    float r0 = rsT[kk+0][b], r1 = rsT[kk+1][b];
                    float r2 = rsT[kk+2][b], r3 = rsT[kk+3][b];
                    float4 u = *(const float4*)(w0 + kw + kk);
                    a0 += r0*u.x + r1*u.y + r2*u.z + r3*u.w;
                }
            }
            if (isA) {
                g_a2T[(size_t)r0g * 64 + b] = a0 +
                    g_qWhT[((size_t)t * kH + r0g) * 64 + b];
            } else {
                g_rtT[(size_t)(r0g - 512) * 64 + b] = ftanh(a0);
            }
        }
        grid_barrier();

        // ---- phase B1: scores; 256 blocks, (bb, quarter-p) each ----
        if (activeA) {
            int bb = blk >> 2;
            int qtr = blk & 3;
            for (int i = tid; i < 512; i += 256)
                a2s[i] = __ldcg(g_a2T + (size_t)i * 64 + bb);
            __syncthreads();

            int wid = tid >> 5, lane = tid & 31;
            int pbase = qtr << 5;
            for (int p = pbase + wid; p < pbase + 32; p += 8) {
                const float* a1p = g_a1 + ((size_t)bb * kPL + p) * kH;
                float part = 0.f;
#pragma unroll
                for (int c2 = 0; c2 < 4; c2++) {
                    int kk = c2 * 128 + (lane << 2);
                    float4 av  = *(const float4*)(a1p + kk);
                    float4 a2v = *(const float4*)&a2s[kk];
                    float4 wv4 = *(const float4*)&wvs[kk];
                    part += wv4.x * htanh(av.x + a2v.x) + wv4.y * htanh(av.y + a2v.y)
                          + wv4.z * htanh(av.z + a2v.z) + wv4.w * htanh(av.w + a2v.w);
                }
#pragma unroll
                for (int o = 16; o; o >>= 1)
                    part += __shfl_xor_sync(0xffffffffu, part, o);
                if (lane == 0) g_ss[bb * kPL + p] = part;
            }
        }
        grid_barrier();

        // ---- phase B2: softmax + r update; blocks 0..63 ----
        if (blk < 64) {
            int bb = blk;
            if (tid < 128) ss[tid] = __ldcg(g_ss + bb * kPL + tid);
            __syncthreads();

            float v = (tid < 128) ? ss[tid] : -3.4e38f;
#pragma unroll
            for (int o = 16; o; o >>= 1) v = fmaxf(v, __shfl_xor_sync(0xffffffffu, v, o));
            if ((tid & 31) == 0) red[tid >> 5] = v;
            __syncthreads();
            float mx = red[0];
#pragma unroll
            for (int w = 1; w < 8; w++) mx = fmaxf(mx, red[w]);
            __syncthreads();
            float e = 0.f;
            if (tid < 128) e = __expf(ss[tid] - mx);
            float sv = e;
#pragma unroll
            for (int o = 16; o; o >>= 1) sv += __shfl_xor_sync(0xffffffffu, sv, o);
            if ((tid & 31) == 0) red[tid >> 5] = sv;
            __syncthreads();
            float tot = 0.f;
#pragma unroll
            for (int w = 0; w < 8; w++) tot += red[w];
            if (tid < 128) ss[tid] = __fdividef(e, tot);
            __syncthreads();

            for (int hh = tid; hh < kH; hh += 256) {
                float acc = __ldcg(g_rtT + (size_t)hh * 64 + bb);
                const float* op = g_outp + (size_t)bb * kPL * kH + hh;
#pragma unroll 8
                for (int p2 = 0; p2 < kPL; p2++)
                    acc += op[(size_t)p2 * kH] * ss[p2];
                g_rT[(size_t)hh * 64 + bb] = acc;
                if (t == kHL - 1) g_r[bb * kH + hh] = acc;
            }
        }
        grid_barrier();
    }
}

// ---------------- final head ----------------
__global__ void __launch_bounds__(128) final_rep(
    const float* __restrict__ w1, const float* __restrict__ b1,
    const float* __restrict__ w2, const float* __restrict__ b2)
{
    __shared__ float rs[64][33];
    __shared__ float hs[64][33];
    int tid = threadIdx.x;
    int b = tid & 63;
    int j = (blockIdx.x << 1) + (tid >> 6);

    float acc1 = 0.f, acc2 = 0.f;
    const float* w1p = w1 + (size_t)j * kH;
    const float* w2p = w2 + (size_t)j * kH;

    for (int k0 = 0; k0 < kH; k0 += 32) {
#pragma unroll
        for (int i = 0; i < 4; i++) {
            int l = i * 128 + tid;
            int row = l >> 3;
            int c4 = (l & 7) << 2;
            float4 rv = *(const float4*)(g_r + row * kH + k0 + c4);
            float4 hv = *(const float4*)(g_hn + row * kH + k0 + c4);
            rs[row][c4 + 0] = rv.x; rs[row][c4 + 1] = rv.y;
            rs[row][c4 + 2] = rv.z; rs[row][c4 + 3] = rv.w;
            hs[row][c4 + 0] = hv.x; hs[row][c4 + 1] = hv.y;
            hs[row][c4 + 2] = hv.z; hs[row][c4 + 3] = hv.w;
        }
        __syncthreads();
#pragma unroll
        for (int k = 0; k < 32; k += 4) {
            float4 w1v = *(const float4*)(w1p + k0 + k);
            float4 w2v = *(const float4*)(w2p + k0 + k);
            acc1 += rs[b][k]*w1v.x + rs[b][k+1]*w1v.y + rs[b][k+2]*w1v.z + rs[b][k+3]*w1v.w;
            acc2 += hs[b][k]*w2v.x + hs[b][k+1]*w2v.y + hs[b][k+2]*w2v.z + hs[b][k+3]*w2v.w;
        }
        __syncthreads();
    }
    g_rep[b * kH + j] = ftanh(acc1 + b1[j] + acc2 + b2[j]);
}

__global__ void final_out_k(const float* __restrict__ fc3w,
                            const float* __restrict__ fc3b, float* __restrict__ out)
{
    int b = blockIdx.x, c = blockIdx.y, lane = threadIdx.x;
    float acc = 0.f;
    for (int k = lane; k < kH; k += 32)
        acc += g_rep[b * kH + k] * fc3w[c * kH + k];
#pragma unroll
    for (int o = 16; o; o >>= 1) acc += __shfl_xor_sync(0xffffffffu, acc, o);
    if (lane == 0) out[b * kC + c] = acc + fc3b[c];
}

// ---------------- launch ----------------
extern "C" void kernel_launch(void* const* d_in, const int* in_sizes, int n_in,
                              void* d_out, int out_size)
{
    const void *p_tokP, *p_tokH, *p_emb, *p_fc3w, *p_fc3b;
    const void *wih[2], *whh[2], *bia[4], *sq[6], *v512[3];
    int nwih, nwhh, nbia, nsq, nv;

    auto try_bind = [&](long long mult) -> bool {
        p_tokP = p_tokH = p_emb = p_fc3w = p_fc3b = 0;
        nwih = nwhh = nbia = nsq = nv = 0;
        for (int i = 0; i < 2; i++) { wih[i] = 0; whh[i] = 0; }
        for (int i = 0; i < 4; i++) bia[i] = 0;
        for (int i = 0; i < 6; i++) sq[i] = 0;
        for (int i = 0; i < 3; i++) v512[i] = 0;
        bool over = false;
        for (int i = 0; i < n_in; i++) {
            long long s = (long long)in_sizes[i];
            const void* p = d_in[i];
            if      (s == (long long)kB * kPL * mult)  { if (p_tokP) over = true; p_tokP = p; }
            else if (s == (long long)kB * kHL * mult)  { if (p_tokH) over = true; p_tokH = p; }
            else if (s == (long long)kV * kE * mult)   { if (p_emb)  over = true; p_emb  = p; }
            else if (s == (long long)kH4 * kE * mult)  { if (nwih < 2) wih[nwih++] = p; else over = true; }
            else if (s == (long long)kH4 * kH * mult)  { if (nwhh < 2) whh[nwhh++] = p; else over = true; }
            else if (s == (long long)kH4 * mult)       { if (nbia < 4) bia[nbia++] = p; else over = true; }
            else if (s == (long long)kH * kH * mult)   { if (nsq  < 6) sq [nsq++]  = p; else over = true; }
            else if (s == (long long)kH * mult)        { if (nv   < 3) v512[nv++]  = p; else over = true; }
            else if (s == (long long)kC * kH * mult)   { if (p_fc3w) over = true; p_fc3w = p; }
            else if (s == (long long)kC * mult)        { if (p_fc3b) over = true; p_fc3b = p; }
        }
        return !over && p_tokP && p_tokH && p_emb && p_fc3w && p_fc3b &&
               nwih == 2 && nwhh == 2 && nbia == 4 && nsq == 6 && nv == 3;
    };

    bool ok = try_bind(1);
    if (!ok) ok = try_bind(4);
    if (!ok && n_in >= 22) {
        p_tokP = d_in[0];  p_tokH = d_in[1];  p_emb = d_in[2];
        wih[0] = d_in[3];  whh[0] = d_in[4];  bia[0] = d_in[5];  bia[1] = d_in[6];
        wih[1] = d_in[7];  whh[1] = d_in[8];  bia[2] = d_in[9];  bia[3] = d_in[10];
        sq[0]  = d_in[11]; sq[1]  = d_in[12]; sq[2]  = d_in[13]; sq[3] = d_in[14];
        v512[0]= d_in[15];
        sq[4]  = d_in[16]; v512[1]= d_in[17];
        sq[5]  = d_in[18]; v512[2]= d_in[19];
        p_fc3w = d_in[20]; p_fc3b = d_in[21];
        ok = true;
    }
    if (!ok) {
        int n = out_size / 4;  if (n < 1) n = 1;
        zero_out_k<<<(n + 255) / 256, 256>>>((float*)d_out, n);
        return;
    }

    const int*   premise = (const int*)p_tokP;
    const int*   hyp     = (const int*)p_tokH;
    const float* emb     = (const float*)p_emb;
    const float* Wih1 = (const float*)wih[0]; const float* Whh1 = (const float*)whh[0];
    const float* Wih2 = (const float*)wih[1]; const float* Whh2 = (const float*)whh[1];
    const float* bih1 = (const float*)bia[0]; const float* bhh1 = (const float*)bia[1];
    const float* bih2 = (const float*)bia[2]; const float* bhh2 = (const float*)bia[3];
    const float* W_y  = (const float*)sq[0];  const float* W_h  = (const float*)sq[1];
    const float* W_r  = (const float*)sq[2];  const float* W_t  = (const float*)sq[3];
    const float* fc1_w= (const float*)sq[4];  const float* fc2_w= (const float*)sq[5];
    const float* w_att= (const float*)v512[0];
    const float* fc1_b= (const float*)v512[1];const float* fc2_b= (const float*)v512[2];
    const float* fc3_w= (const float*)p_fc3w; const float* fc3_b= (const float*)p_fc3b;
    float* out = (float*)d_out;

    zero_init<<<128, 256>>>();

    dim3 gP(kH4 / 64, (kPL * kB) / 64);
    gemm64<<<gP, 256>>>(0, emb, premise, Wih1, bih1, bhh1, kH4, kE, kPL);
    dim3 gHyp(kH4 / 64, (kHL * kB) / 64);
    gemm64<<<gHyp, 256>>>(1, emb, hyp, Wih2, bih2, bhh2, kH4, kE, kHL);

    lstm_persist<<<NBLKP, 256>>>(Whh1, Whh2);

    dim3 gA1(kH / 64, (kB * kPL) / 64);
    gemm64<<<gA1, 256>>>(2, nullptr, nullptr, W_y, nullptr, nullptr, kH, kH, 0);
    dim3 gQ(kH / 64, (kB * kHL) / 64);
    gemm64<<<gQ, 256>>>(3, nullptr, nullptr, W_h, nullptr, nullptr, kH, kH, 0);

    att_persist<<<NBLKP, 256>>>(W_r, W_t, w_att);

    final_rep<<<256, 128>>>(fc1_w, fc1_b, fc2_w, fc2_b);
    dim3 gO(kB, kC);
    final_out_k<<<gO, 32>>>(fc3_w, fc3_b, out);
}